// round 1
// baseline (speedup 1.0000x reference)
#include <cuda_runtime.h>
#include <cuda_bf16.h>
#include <cstdint>

// Problem constants (shapes fixed by the reference)
#define C_DIM 64
#define K_DIM 32
#define B_DIM 16
#define EPSF  1e-9f

// Output layout (tuple flattened in return order):
// out[B,K,C]=32768 | s[N,K]=N*32 | entropy | diversity | spatial | pruning |
// sparsity | separation | mu[B,K,2]=1024
#define OFF_OUT   0
#define OUT_ELEMS (B_DIM * K_DIM * C_DIM)              // 32768
#define OFF_S     OUT_ELEMS

// ---------------- device scratch (no allocations allowed) ----------------
__device__ float g_ent;                       // sum over nodes of sum_k s*log(s+eps)
__device__ float g_ss[B_DIM * K_DIM];         // per-graph sum of s        [B,K]
__device__ float g_spp[B_DIM * K_DIM * 2];    // per-graph sum of s*pos    [B,K,2]
__device__ float g_spq[K_DIM];                // global sum of s*|pos|^2   [K]
__device__ int   g_start[B_DIM + 1];          // graph start offsets

// ---------------- packed f32x2 helpers ----------------
__device__ __forceinline__ unsigned long long pack2(float lo, float hi) {
    unsigned long long r;
    asm("mov.b64 %0, {%1, %2};" : "=l"(r) : "f"(lo), "f"(hi));
    return r;
}
__device__ __forceinline__ void unpack2(unsigned long long v, float& lo, float& hi) {
    asm("mov.b64 {%0, %1}, %2;" : "=f"(lo), "=f"(hi) : "l"(v));
}
__device__ __forceinline__ unsigned long long fma2(unsigned long long a,
                                                   unsigned long long b,
                                                   unsigned long long c) {
    unsigned long long d;
    asm("fma.rn.f32x2 %0, %1, %2, %3;" : "=l"(d) : "l"(a), "l"(b), "l"(c));
    return d;
}

// ---------------- kernel 0: zero scratch + out region ----------------
__global__ void hp_zero_kernel(float* __restrict__ out, int N) {
    int i = blockIdx.x * blockDim.x + threadIdx.x;
    int stride = gridDim.x * blockDim.x;
    for (int j = i; j < OUT_ELEMS; j += stride) out[j] = 0.0f;
    for (int j = i; j < B_DIM * K_DIM; j += stride) {
        g_ss[j] = 0.0f;
        g_spp[2 * j] = 0.0f;
        g_spp[2 * j + 1] = 0.0f;
    }
    if (i < K_DIM) g_spq[i] = 0.0f;
    if (i == 0) g_ent = 0.0f;
    if (i <= B_DIM) g_start[i] = N;   // sentinel; g_start[B]=N is final
}

// ---------------- kernel 1: graph boundaries (batch is sorted) ----------------
__global__ void hp_bound_kernel(const int* __restrict__ batch, int N) {
    int n = blockIdx.x * blockDim.x + threadIdx.x;
    int stride = gridDim.x * blockDim.x;
    for (; n < N; n += stride) {
        if (n == 0 || batch[n] != batch[n - 1]) {
            atomicMin(&g_start[batch[n]], n);
        }
    }
}
__global__ void hp_fix_kernel(int N) {
    g_start[B_DIM] = N;
    for (int b = B_DIM - 1; b >= 0; b--)
        if (g_start[b] > g_start[b + 1]) g_start[b] = g_start[b + 1];
}

// ---------------- kernel A: MLP + gumbel softmax -> s, entropy ----------------
__global__ __launch_bounds__(256)
void hp_assign_kernel(const float* __restrict__ x,
                      const float* __restrict__ u,
                      const float* __restrict__ W1,
                      const float* __restrict__ b1,
                      const float* __restrict__ W2,
                      const float* __restrict__ b2,
                      const float* __restrict__ scaling,
                      const float* __restrict__ amask,
                      float* __restrict__ s_out,
                      int N) {
    __shared__ __align__(16) float W1s[C_DIM * C_DIM];   // [j][i] row-major, 16KB
    __shared__ __align__(16) float W2s[C_DIM * K_DIM];   // [i][k] row-major, 8KB
    __shared__ __align__(16) float b1s[C_DIM];
    __shared__ __align__(16) float b2s[K_DIM];
    __shared__ float msk[K_DIM];
    __shared__ float scal;

    int t = threadIdx.x;
    for (int i = t; i < C_DIM * C_DIM; i += 256) W1s[i] = W1[i];
    for (int i = t; i < C_DIM * K_DIM; i += 256) W2s[i] = W2[i];
    if (t < C_DIM) b1s[t] = b1[t];
    if (t < K_DIM) { b2s[t] = b2[t]; msk[t] = amask[t]; }
    if (t == 0) scal = scaling[0];
    __syncthreads();

    int n = blockIdx.x * 256 + t;
    float ent_local = 0.0f;

    if (n < N) {
        // ---- hidden = relu(x @ W1 + b1), packed f32x2 accumulators ----
        unsigned long long h2[C_DIM / 2];
        #pragma unroll
        for (int i = 0; i < C_DIM / 2; i++) h2[i] = pack2(b1s[2 * i], b1s[2 * i + 1]);

        const float4* xv = (const float4*)(x + (size_t)n * C_DIM);
        const ulonglong2* W1q = (const ulonglong2*)W1s;  // [j*16 + i2]
        #pragma unroll
        for (int jc = 0; jc < 16; jc++) {
            float4 xq = xv[jc];
            float xe[4] = {xq.x, xq.y, xq.z, xq.w};
            #pragma unroll
            for (int q = 0; q < 4; q++) {
                int j = jc * 4 + q;
                unsigned long long x2 = pack2(xe[q], xe[q]);
                #pragma unroll
                for (int i2 = 0; i2 < 16; i2++) {
                    ulonglong2 w = W1q[j * 16 + i2];
                    h2[2 * i2]     = fma2(x2, w.x, h2[2 * i2]);
                    h2[2 * i2 + 1] = fma2(x2, w.y, h2[2 * i2 + 1]);
                }
            }
        }

        // ---- logits = relu(h) @ W2 + b2, packed ----
        unsigned long long l2[K_DIM / 2];
        #pragma unroll
        for (int k = 0; k < K_DIM / 2; k++) l2[k] = pack2(b2s[2 * k], b2s[2 * k + 1]);

        const ulonglong2* W2q = (const ulonglong2*)W2s;  // [i*8 + k2]
        #pragma unroll
        for (int ih = 0; ih < C_DIM / 2; ih++) {
            float h0, h1;
            unpack2(h2[ih], h0, h1);
            h0 = fmaxf(h0, 0.0f);
            h1 = fmaxf(h1, 0.0f);
            unsigned long long ha = pack2(h0, h0);
            unsigned long long hb = pack2(h1, h1);
            int i0 = 2 * ih, i1 = 2 * ih + 1;
            #pragma unroll
            for (int k2 = 0; k2 < 8; k2++) {
                ulonglong2 wa = W2q[i0 * 8 + k2];
                l2[2 * k2]     = fma2(ha, wa.x, l2[2 * k2]);
                l2[2 * k2 + 1] = fma2(ha, wa.y, l2[2 * k2 + 1]);
            }
            #pragma unroll
            for (int k2 = 0; k2 < 8; k2++) {
                ulonglong2 wb = W2q[i1 * 8 + k2];
                l2[2 * k2]     = fma2(hb, wb.x, l2[2 * k2]);
                l2[2 * k2 + 1] = fma2(hb, wb.y, l2[2 * k2 + 1]);
            }
        }

        float l[K_DIM];
        #pragma unroll
        for (int k = 0; k < K_DIM / 2; k++) unpack2(l2[k], l[2 * k], l[2 * k + 1]);

        // ---- scale, mask, gumbel, softmax ----
        const float4* uv = (const float4*)(u + (size_t)n * K_DIM);
        float z[K_DIM];
        float m = -3.4e38f;
        #pragma unroll
        for (int kc = 0; kc < 8; kc++) {
            float4 uq = uv[kc];
            float ue[4] = {uq.x, uq.y, uq.z, uq.w};
            #pragma unroll
            for (int q = 0; q < 4; q++) {
                int k = kc * 4 + q;
                float lg = l[k] * scal;
                lg = (msk[k] == 0.0f) ? -1e9f : lg;
                float g = -__logf(-__logf(ue[q] + EPSF) + EPSF);
                float zz = lg + g;   // TAU = 1
                z[k] = zz;
                m = fmaxf(m, zz);
            }
        }
        float ssum = 0.0f;
        #pragma unroll
        for (int k = 0; k < K_DIM; k++) {
            float e = __expf(z[k] - m);
            z[k] = e;
            ssum += e;
        }
        float inv = 1.0f / ssum;

        float4* so = (float4*)(s_out + (size_t)n * K_DIM);
        #pragma unroll
        for (int kc = 0; kc < 8; kc++) {
            float s0 = z[kc * 4 + 0] * inv;
            float s1 = z[kc * 4 + 1] * inv;
            float s2 = z[kc * 4 + 2] * inv;
            float s3 = z[kc * 4 + 3] * inv;
            ent_local += s0 * __logf(s0 + EPSF) + s1 * __logf(s1 + EPSF)
                       + s2 * __logf(s2 + EPSF) + s3 * __logf(s3 + EPSF);
            so[kc] = make_float4(s0, s1, s2, s3);
        }
    }

    // block-reduce entropy contribution, one atomic per block
    #pragma unroll
    for (int o = 16; o; o >>= 1) ent_local += __shfl_xor_sync(0xffffffffu, ent_local, o);
    __shared__ float wsum[8];
    if ((t & 31) == 0) wsum[t >> 5] = ent_local;
    __syncthreads();
    if (t < 8) {
        float w = wsum[t];
        #pragma unroll
        for (int o = 4; o; o >>= 1) w += __shfl_xor_sync(0xffu, w, o);
        if (t == 0) atomicAdd(&g_ent, w);
    }
}

// ---------------- kernel B: per-graph pooled features + centroid sums ----------------
#define SPLITS 32
__global__ __launch_bounds__(256)
void hp_pool_kernel(const float* __restrict__ x,
                    const float* __restrict__ pos,
                    const float* __restrict__ s,
                    float* __restrict__ out) {
    int b = blockIdx.y;
    int n0 = g_start[b], n1 = g_start[b + 1];
    int cnt = n1 - n0;
    int chunk = (cnt + SPLITS - 1) / SPLITS;
    int s0 = n0 + blockIdx.x * chunk;
    int s1 = min(s0 + chunk, n1);
    if (s0 >= s1) return;

    __shared__ float ssh[32][33];
    __shared__ float xsh[32][65];
    __shared__ float psh[32][2];

    int t = threadIdx.x;
    int k = t & 31;
    int grp = t >> 5;   // 0..7, uniform per warp

    float acc[8] = {0, 0, 0, 0, 0, 0, 0, 0};
    float ass = 0.0f, apx = 0.0f, apy = 0.0f, aq = 0.0f;

    for (int base = s0; base < s1; base += 32) {
        // stage s tile [32 nodes][32 k] (zero-padded)
        for (int r = grp; r < 32; r += 8) {
            ssh[r][k] = (base + r < s1) ? s[(size_t)(base + r) * K_DIM + k] : 0.0f;
        }
        // stage x tile [32][64]
        for (int idx = t; idx < 32 * 64; idx += 256) {
            int r = idx >> 6, c = idx & 63;
            xsh[r][c] = (base + r < s1) ? x[(size_t)(base + r) * C_DIM + c] : 0.0f;
        }
        // stage pos tile [32][2]
        if (t < 64) {
            int r = t >> 1, d = t & 1;
            psh[r][d] = (base + r < s1) ? pos[(size_t)(base + r) * 2 + d] : 0.0f;
        }
        __syncthreads();

        #pragma unroll 4
        for (int nn = 0; nn < 32; nn++) {
            float sv = ssh[nn][k];
            if (grp == 0) {
                float px = psh[nn][0], py = psh[nn][1];
                ass += sv;
                apx += sv * px;
                apy += sv * py;
                aq  += sv * (px * px + py * py);
            }
            #pragma unroll
            for (int j = 0; j < 8; j++) acc[j] += sv * xsh[nn][grp * 8 + j];
        }
        __syncthreads();
    }

    #pragma unroll
    for (int j = 0; j < 8; j++)
        atomicAdd(&out[OFF_OUT + ((size_t)b * K_DIM + k) * C_DIM + grp * 8 + j], acc[j]);
    if (grp == 0) {
        int bk = b * K_DIM + k;
        atomicAdd(&g_ss[bk], ass);
        atomicAdd(&g_spp[2 * bk + 0], apx);
        atomicAdd(&g_spp[2 * bk + 1], apy);
        atomicAdd(&g_spq[k], aq);
    }
}

// ---------------- kernel C: finalize scalars, mu, separation ----------------
__global__ __launch_bounds__(512)
void hp_final_kernel(const float* __restrict__ amask, float* __restrict__ out, int N) {
    __shared__ float mush[B_DIM * K_DIM][2];
    __shared__ float red[16];

    // offsets into out
    const size_t off_scalars = (size_t)OFF_S + (size_t)N * K_DIM;
    const size_t OFF_ENT  = off_scalars + 0;
    const size_t OFF_DIV  = off_scalars + 1;
    const size_t OFF_SPAT = off_scalars + 2;
    const size_t OFF_PRUN = off_scalars + 3;
    const size_t OFF_SPAR = off_scalars + 4;
    const size_t OFF_SEP  = off_scalars + 5;
    const size_t OFF_MU   = off_scalars + 6;

    int t = threadIdx.x;        // 512 = B*K
    int bk = t;
    float ssv = g_ss[bk];
    float denom = ssv + EPSF;
    float mux = g_spp[2 * bk] / denom;
    float muy = g_spp[2 * bk + 1] / denom;
    mush[bk][0] = mux;
    mush[bk][1] = muy;
    out[OFF_MU + 2 * bk] = mux;
    out[OFF_MU + 2 * bk + 1] = muy;
    __syncthreads();

    // separation: sum over b of off-diagonal 1/(d^2+1)
    int b = bk >> 5, k1 = bk & 31;
    float sep = 0.0f;
    #pragma unroll
    for (int k2 = 0; k2 < K_DIM; k2++) {
        if (k2 == k1) continue;
        float dx = mux - mush[b * K_DIM + k2][0];
        float dy = muy - mush[b * K_DIM + k2][1];
        sep += 1.0f / (dx * dx + dy * dy + 1.0f);
    }
    #pragma unroll
    for (int o = 16; o; o >>= 1) sep += __shfl_xor_sync(0xffffffffu, sep, o);
    if ((t & 31) == 0) red[t >> 5] = sep;
    __syncthreads();

    if (t == 0) {
        float tot = 0.0f;
        for (int i = 0; i < 16; i++) tot += red[i];
        out[OFF_SEP] = tot / ((float)(K_DIM * (K_DIM - 1)) + EPSF);

        float div = 0.0f, spat = 0.0f, prun = 0.0f, spars = 0.0f;
        for (int k = 0; k < K_DIM; k++) {
            float ss = 0.0f, sx = 0.0f, sy = 0.0f;
            for (int bb = 0; bb < B_DIM; bb++) {
                int idx = bb * K_DIM + k;
                ss += g_ss[idx];
                sx += g_spp[2 * idx];
                sy += g_spp[2 * idx + 1];
            }
            float avg = ss / (float)N;
            div += avg * __logf(avg + EPSF);
            float sse = ss + EPSF;
            float mgx = sx / sse, mgy = sy / sse;
            float var = g_spq[k] / sse
                        - 2.0f * (mgx * (sx / sse) + mgy * (sy / sse))
                        + (mgx * mgx + mgy * mgy);
            spat += var;
            float mk = amask[k];
            prun += fabsf(avg * (1.0f - mk));
            spars += mk;
        }
        out[OFF_ENT]  = -g_ent / (float)N;
        out[OFF_DIV]  = div;
        out[OFF_SPAT] = spat / (float)K_DIM;
        out[OFF_PRUN] = prun / (float)K_DIM;
        out[OFF_SPAR] = spars / (float)K_DIM;
    }
}

// ---------------- launcher ----------------
extern "C" void kernel_launch(void* const* d_in, const int* in_sizes, int n_in,
                              void* d_out, int out_size) {
    (void)n_in; (void)out_size;
    const float* x       = (const float*)d_in[0];
    const int*   batch   = (const int*)d_in[1];
    const float* pos     = (const float*)d_in[2];
    const float* u       = (const float*)d_in[3];
    const float* W1      = (const float*)d_in[4];
    const float* b1      = (const float*)d_in[5];
    const float* W2      = (const float*)d_in[6];
    const float* b2      = (const float*)d_in[7];
    const float* scaling = (const float*)d_in[8];
    const float* amask   = (const float*)d_in[9];
    float* out = (float*)d_out;

    int N = in_sizes[0] / C_DIM;

    hp_zero_kernel<<<64, 256>>>(out, N);
    hp_bound_kernel<<<256, 256>>>(batch, N);
    hp_fix_kernel<<<1, 1>>>(N);
    hp_assign_kernel<<<(N + 255) / 256, 256>>>(x, u, W1, b1, W2, b2, scaling, amask,
                                               out + OFF_S, N);
    hp_pool_kernel<<<dim3(SPLITS, B_DIM), 256>>>(x, pos, out + OFF_S, out);
    hp_final_kernel<<<1, 512>>>(amask, out, N);
}